// round 10
// baseline (speedup 1.0000x reference)
#include <cuda_runtime.h>
#include <cuda_fp16.h>
#include <cuda_bf16.h>
#include <stdint.h>

#define BDIM 4096
#define PDIM 512
#define IDIM 1024
#define FDIM 2048

// ---------------- scratch (device globals; allocation-free rule) ----------------
__device__ __align__(128) __half g_xh[(size_t)BDIM * IDIM];
__device__ __align__(128) __half g_fh[(size_t)FDIM * IDIM];
__device__ __align__(128) __half g_ph[(size_t)PDIM * IDIM];
__device__ __align__(128) __nv_bfloat16 g_a[(size_t)BDIM * FDIM];  // xf*relu(xf)
__device__ __align__(128) __nv_bfloat16 g_w[(size_t)BDIM * FDIM];  // -beta*(1-relu(xf))
__device__ __align__(128) __nv_bfloat16 g_v[(size_t)PDIM * FDIM];  // theta*c - alpha*(1-relu(pf))
__device__ __align__(128) __nv_bfloat16 g_c[(size_t)PDIM * FDIM];  // pf*relu(pf)

// ---------------- helpers ----------------
__device__ __forceinline__ uint32_t s2u(const void* p) {
    uint32_t a;
    asm("{ .reg .u64 t; cvta.to.shared.u64 t, %1; cvt.u32.u64 %0, t; }" : "=r"(a) : "l"(p));
    return a;
}

#define CP16(dst, src) \
    asm volatile("cp.async.cg.shared.global [%0], [%1], 16;" :: "r"(dst), "l"(src))
#define CPCOMMIT() asm volatile("cp.async.commit_group;")
#define CPWAIT(n)  asm volatile("cp.async.wait_group %0;" :: "n"(n))

__device__ __forceinline__ void ldsm4(uint32_t& r0, uint32_t& r1, uint32_t& r2, uint32_t& r3,
                                      uint32_t addr) {
    asm volatile("ldmatrix.sync.aligned.m8n8.x4.shared.b16 {%0,%1,%2,%3}, [%4];"
                 : "=r"(r0), "=r"(r1), "=r"(r2), "=r"(r3) : "r"(addr));
}

__device__ __forceinline__ void mma_f16(float c[4], const uint32_t a[4], const uint32_t b[2]) {
    asm volatile(
        "mma.sync.aligned.m16n8k16.row.col.f32.f16.f16.f32 "
        "{%0,%1,%2,%3}, {%4,%5,%6,%7}, {%8,%9}, {%0,%1,%2,%3};"
        : "+f"(c[0]), "+f"(c[1]), "+f"(c[2]), "+f"(c[3])
        : "r"(a[0]), "r"(a[1]), "r"(a[2]), "r"(a[3]), "r"(b[0]), "r"(b[1]));
}

__device__ __forceinline__ void mma_bf16(float c[4], const uint32_t a[4], const uint32_t b[2]) {
    asm volatile(
        "mma.sync.aligned.m16n8k16.row.col.f32.bf16.bf16.f32 "
        "{%0,%1,%2,%3}, {%4,%5,%6,%7}, {%8,%9}, {%0,%1,%2,%3};"
        : "+f"(c[0]), "+f"(c[1]), "+f"(c[2]), "+f"(c[3])
        : "r"(a[0]), "r"(a[1]), "r"(a[2]), "r"(a[3]), "r"(b[0]), "r"(b[1]));
}

// ---------------- merged fp32 -> fp16 conversion (one launch) ----------------
__global__ void cvt_all(const float4* __restrict__ x, const float4* __restrict__ f,
                        const float4* __restrict__ p)
{
    const int nx = BDIM * IDIM / 4, nf = FDIM * IDIM / 4, np = PDIM * IDIM / 4;
    int i = blockIdx.x * blockDim.x + threadIdx.x;
    const float4* src; uint2* dst; int j;
    if (i < nx)                { src = x; dst = (uint2*)g_xh; j = i; }
    else if (i < nx + nf)      { src = f; dst = (uint2*)g_fh; j = i - nx; }
    else if (i < nx + nf + np) { src = p; dst = (uint2*)g_ph; j = i - nx - nf; }
    else return;
    float4 v = src[j];
    __half2 h0 = __floats2half2_rn(v.x, v.y);
    __half2 h1 = __floats2half2_rn(v.z, v.w);
    uint2 o; o.x = *(uint32_t*)&h0; o.y = *(uint32_t*)&h1;
    dst[j] = o;
}

// =================================================================
// Stage 1 (fp16 m16n8k16): Y = In @ Feat^T, merged x/proto grids.
// CTA 128x128, 128 threads, 4 warps (2x2), warp tile 64x64,
// k-tile 32, 4-stage cp.async, fragment double-buffering.
// =================================================================
#define SROW 40                            // 32 data + 8 pad halfs (80 B row)
#define S1_STAGE_E (256 * SROW)
#define S1_STAGE_B (S1_STAGE_E * 2)        // 20480 bytes
#define STAGES1 4
#define S1_SMEM (STAGES1 * S1_STAGE_B)     // 81920 bytes

__global__ __launch_bounds__(128, 2)
void s1_kernel(const float* __restrict__ alpha, const float* __restrict__ beta,
               const float* __restrict__ theta)
{
    extern __shared__ __half sm1[];
    const uint32_t sb = s2u(sm1);
    const int tid = threadIdx.x;
    const int wid = tid >> 5, lid = tid & 31;
    const int g = lid >> 2, tg = lid & 3;
    const int wm = wid >> 1, wn = wid & 1;
    const int rb = blockIdx.y;
    const bool isX = rb < (BDIM / 128);
    const int row0 = (isX ? rb : rb - BDIM / 128) * 128;
    const int col0 = blockIdx.x * 128;

    const __half* In = isX ? g_xh : g_ph;
    __nv_bfloat16* out1 = isX ? g_a : g_v;
    __nv_bfloat16* out2 = isX ? g_w : g_c;

    const int r0 = tid >> 2, ch = tid & 3;
    const __half* srcA = In   + (size_t)(row0 + r0) * IDIM + ch * 8;
    const __half* srcB = g_fh + (size_t)(col0 + r0) * IDIM + ch * 8;
    const int dBase = r0 * SROW + ch * 8;

    const int aOff = ((lid & 7) + ((lid >> 3) & 1) * 8) * SROW + (lid >> 4) * 8;
    const int bOff = ((lid & 7) + (lid >> 4) * 8) * SROW + ((lid >> 3) & 1) * 8;

    float acc[4][8][4];
#pragma unroll
    for (int mi = 0; mi < 4; mi++)
#pragma unroll
        for (int ni = 0; ni < 8; ni++)
#pragma unroll
            for (int j = 0; j < 4; j++) acc[mi][ni][j] = 0.f;

    const int NIT = IDIM / 32;

#pragma unroll
    for (int s = 0; s < STAGES1 - 1; s++) {
        __half* st = sm1 + s * S1_STAGE_E;
        const int k0 = s * 32;
#pragma unroll
        for (int i = 0; i < 4; i++) {
            CP16(s2u(st + dBase + i * 32 * SROW), srcA + (size_t)(i * 32) * IDIM + k0);
            CP16(s2u(st + dBase + (128 + i * 32) * SROW), srcB + (size_t)(i * 32) * IDIM + k0);
        }
        CPCOMMIT();
    }

    for (int it = 0; it < NIT; it++) {
        CPWAIT(STAGES1 - 2);
        __syncthreads();

        const int nxt = it + STAGES1 - 1;
        if (nxt < NIT) {
            __half* st = sm1 + (nxt % STAGES1) * S1_STAGE_E;
            const int k0 = nxt * 32;
#pragma unroll
            for (int i = 0; i < 4; i++) {
                CP16(s2u(st + dBase + i * 32 * SROW), srcA + (size_t)(i * 32) * IDIM + k0);
                CP16(s2u(st + dBase + (128 + i * 32) * SROW), srcB + (size_t)(i * 32) * IDIM + k0);
            }
        }
        CPCOMMIT();

        const uint32_t su = sb + (it % STAGES1) * S1_STAGE_B;
        const uint32_t aBase = su + 2 * (wm * 64 * SROW + aOff);
        const uint32_t bBase = su + 2 * ((128 + wn * 64) * SROW + bOff);

        uint32_t af[2][4][4], bf[2][8][2];
#pragma unroll
        for (int mi = 0; mi < 4; mi++)
            ldsm4(af[0][mi][0], af[0][mi][1], af[0][mi][2], af[0][mi][3],
                  aBase + 2 * (mi * 16 * SROW));
#pragma unroll
        for (int nb = 0; nb < 4; nb++)
            ldsm4(bf[0][2 * nb][0], bf[0][2 * nb][1], bf[0][2 * nb + 1][0], bf[0][2 * nb + 1][1],
                  bBase + 2 * (nb * 16 * SROW));

#pragma unroll
        for (int ks = 0; ks < 2; ks++) {
            const int cur = ks & 1, nx2 = cur ^ 1;
            if (ks < 1) {
                const int kk = 16;
#pragma unroll
                for (int mi = 0; mi < 4; mi++)
                    ldsm4(af[nx2][mi][0], af[nx2][mi][1], af[nx2][mi][2], af[nx2][mi][3],
                          aBase + 2 * (mi * 16 * SROW + kk));
#pragma unroll
                for (int nb = 0; nb < 4; nb++)
                    ldsm4(bf[nx2][2 * nb][0], bf[nx2][2 * nb][1],
                          bf[nx2][2 * nb + 1][0], bf[nx2][2 * nb + 1][1],
                          bBase + 2 * (nb * 16 * SROW + kk));
            }
#pragma unroll
            for (int mi = 0; mi < 4; mi++)
#pragma unroll
                for (int ni = 0; ni < 8; ni++)
                    mma_f16(acc[mi][ni], af[cur][mi], bf[cur][ni]);
        }
    }

    const float al = __ldg(alpha);
    const float be = __ldg(beta);
    const float th = __ldg(theta);

#pragma unroll
    for (int mi = 0; mi < 4; mi++)
#pragma unroll
        for (int ni = 0; ni < 8; ni++) {
            const int rr = row0 + wm * 64 + mi * 16 + g;
            const int cc = col0 + wn * 64 + ni * 8 + tg * 2;
#pragma unroll
            for (int h = 0; h < 2; h++) {
                const float y0 = acc[mi][ni][h * 2 + 0];
                const float y1 = acc[mi][ni][h * 2 + 1];
                const float p0 = fmaxf(y0, 0.f), p1 = fmaxf(y1, 0.f);
                const float yp0 = y0 * p0, yp1 = y1 * p1;
                const float iv0 = 1.f - p0, iv1 = 1.f - p1;
                float o1a, o1b, o2a, o2b;
                if (isX) { o1a = yp0;                  o1b = yp1;
                           o2a = -be * iv0;            o2b = -be * iv1; }
                else     { o1a = th * yp0 - al * iv0;  o1b = th * yp1 - al * iv1;
                           o2a = yp0;                  o2b = yp1; }
                const size_t off = (size_t)(rr + h * 8) * FDIM + cc;
                *(__nv_bfloat162*)&out1[off] = __floats2bfloat162_rn(o1a, o1b);
                *(__nv_bfloat162*)&out2[off] = __floats2bfloat162_rn(o2a, o2b);
            }
        }
}

// =================================================================
// Stage 2 (bf16 m16n8k16): out = a @ v^T + w @ c^T (two k-phases over F)
// CTA 128x64, 64 threads, 2 warps (2x1), warp tile 64x64,
// k-tile 32, 3-stage cp.async, fragment double-buffering.
// =================================================================
#define STAGES2 3
#define S2_STAGE_E (192 * SROW)            // 128 A rows + 64 B rows
#define S2_STAGE_B (S2_STAGE_E * 2)        // 15360 bytes
#define S2_SMEM    (STAGES2 * S2_STAGE_B)  // 46080 bytes
#define NIT2 (2 * FDIM / 32)               // 128
#define HALF2N (FDIM / 32)                 // 64

__global__ __launch_bounds__(64, 4)
void s2_kernel(float* __restrict__ Out)
{
    extern __shared__ __nv_bfloat16 sm2[];
    const uint32_t sb = s2u(sm2);
    const int tid = threadIdx.x;
    const int wid = tid >> 5, lid = tid & 31;
    const int g = lid >> 2, tg = lid & 3;
    const int wm = wid;                                 // 2 warps stacked in M
    const int row0 = blockIdx.y * 128;
    const int col0 = blockIdx.x * 64;

    // loader: 768 cp16 per stage / 64 threads = 12 each (8 A rows + 4 B rows)
    const int r0 = tid >> 2, ch = tid & 3;              // r0: 0..15, ch: 0..3
    const int dBase = r0 * SROW + ch * 8;

    const int aOff = ((lid & 7) + ((lid >> 3) & 1) * 8) * SROW + (lid >> 4) * 8;
    const int bOff = ((lid & 7) + (lid >> 4) * 8) * SROW + ((lid >> 3) & 1) * 8;

    float acc[4][8][4];
#pragma unroll
    for (int mi = 0; mi < 4; mi++)
#pragma unroll
        for (int ni = 0; ni < 8; ni++)
#pragma unroll
            for (int j = 0; j < 4; j++) acc[mi][ni][j] = 0.f;

#pragma unroll
    for (int s = 0; s < STAGES2 - 1; s++) {
        __nv_bfloat16* st = sm2 + s * S2_STAGE_E;
        const __nv_bfloat16* A = (s < HALF2N) ? g_a : g_w;
        const __nv_bfloat16* B = (s < HALF2N) ? g_v : g_c;
        const int k0 = (s & (HALF2N - 1)) * 32;
#pragma unroll
        for (int i = 0; i < 8; i++)
            CP16(s2u(st + dBase + i * 16 * SROW),
                 A + (size_t)(row0 + r0 + i * 16) * FDIM + k0 + ch * 8);
#pragma unroll
        for (int i = 0; i < 4; i++)
            CP16(s2u(st + dBase + (128 + i * 16) * SROW),
                 B + (size_t)(col0 + r0 + i * 16) * FDIM + k0 + ch * 8);
        CPCOMMIT();
    }

    for (int it = 0; it < NIT2; it++) {
        CPWAIT(STAGES2 - 2);
        __syncthreads();

        const int nxt = it + STAGES2 - 1;
        if (nxt < NIT2) {
            __nv_bfloat16* st = sm2 + (nxt % STAGES2) * S2_STAGE_E;
            const __nv_bfloat16* A = (nxt < HALF2N) ? g_a : g_w;
            const __nv_bfloat16* B = (nxt < HALF2N) ? g_v : g_c;
            const int k0 = (nxt & (HALF2N - 1)) * 32;
#pragma unroll
            for (int i = 0; i < 8; i++)
                CP16(s2u(st + dBase + i * 16 * SROW),
                     A + (size_t)(row0 + r0 + i * 16) * FDIM + k0 + ch * 8);
#pragma unroll
            for (int i = 0; i < 4; i++)
                CP16(s2u(st + dBase + (128 + i * 16) * SROW),
                     B + (size_t)(col0 + r0 + i * 16) * FDIM + k0 + ch * 8);
        }
        CPCOMMIT();

        const uint32_t su = sb + (it % STAGES2) * S2_STAGE_B;
        const uint32_t aBase = su + 2 * (wm * 64 * SROW + aOff);
        const uint32_t bBase = su + 2 * (128 * SROW + bOff);

        uint32_t af[2][4][4], bf[2][8][2];
#pragma unroll
        for (int mi = 0; mi < 4; mi++)
            ldsm4(af[0][mi][0], af[0][mi][1], af[0][mi][2], af[0][mi][3],
                  aBase + 2 * (mi * 16 * SROW));
#pragma unroll
        for (int nb = 0; nb < 4; nb++)
            ldsm4(bf[0][2 * nb][0], bf[0][2 * nb][1], bf[0][2 * nb + 1][0], bf[0][2 * nb + 1][1],
                  bBase + 2 * (nb * 16 * SROW));

#pragma unroll
        for (int ks = 0; ks < 2; ks++) {
            const int cur = ks & 1, nx2 = cur ^ 1;
            if (ks < 1) {
                const int kk = 16;
#pragma unroll
                for (int mi = 0; mi < 4; mi++)
                    ldsm4(af[nx2][mi][0], af[nx2][mi][1], af[nx2][mi][2], af[nx2][mi][3],
                          aBase + 2 * (mi * 16 * SROW + kk));
#pragma unroll
                for (int nb = 0; nb < 4; nb++)
                    ldsm4(bf[nx2][2 * nb][0], bf[nx2][2 * nb][1],
                          bf[nx2][2 * nb + 1][0], bf[nx2][2 * nb + 1][1],
                          bBase + 2 * (nb * 16 * SROW + kk));
            }
#pragma unroll
            for (int mi = 0; mi < 4; mi++)
#pragma unroll
                for (int ni = 0; ni < 8; ni++)
                    mma_bf16(acc[mi][ni], af[cur][mi], bf[cur][ni]);
        }
    }

#pragma unroll
    for (int mi = 0; mi < 4; mi++)
#pragma unroll
        for (int ni = 0; ni < 8; ni++) {
            const int rr = row0 + wm * 64 + mi * 16 + g;
            const int cc = col0 + ni * 8 + tg * 2;
#pragma unroll
            for (int h = 0; h < 2; h++) {
                float2 o = { acc[mi][ni][h * 2 + 0], acc[mi][ni][h * 2 + 1] };
                *(float2*)&Out[(size_t)(rr + h * 8) * PDIM + cc] = o;
            }
        }
}

// ---------------- launch ----------------
extern "C" void kernel_launch(void* const* d_in, const int* in_sizes, int n_in,
                              void* d_out, int out_size)
{
    const float* x     = (const float*)d_in[0];
    const float* feat  = (const float*)d_in[1];
    const float* proto = (const float*)d_in[2];
    const float* alpha = (const float*)d_in[3];
    const float* beta  = (const float*)d_in[4];
    const float* theta = (const float*)d_in[5];
    float* out = (float*)d_out;

    static bool attr_done = false;
    if (!attr_done) {
        cudaFuncSetAttribute(s1_kernel, cudaFuncAttributeMaxDynamicSharedMemorySize, S1_SMEM);
        cudaFuncSetAttribute(s2_kernel, cudaFuncAttributeMaxDynamicSharedMemorySize, S2_SMEM);
        attr_done = true;
    }

    const int ntot = (BDIM + FDIM + PDIM) * IDIM / 4;
    cvt_all<<<(ntot + 255) / 256, 256>>>((const float4*)x, (const float4*)feat,
                                         (const float4*)proto);
    s1_kernel<<<dim3(FDIM / 128, (BDIM + PDIM) / 128), 128, S1_SMEM>>>(alpha, beta, theta);
    s2_kernel<<<dim3(PDIM / 64, BDIM / 128), 64, S2_SMEM>>>(out);
}

// round 12
// speedup vs baseline: 1.0869x; 1.0869x over previous
#include <cuda_runtime.h>
#include <cuda_fp16.h>
#include <cuda_bf16.h>
#include <stdint.h>

#define BDIM 4096
#define PDIM 512
#define IDIM 1024
#define FDIM 2048

// ---------------- scratch (device globals; allocation-free rule) ----------------
__device__ __align__(128) __half g_xh[(size_t)BDIM * IDIM];
__device__ __align__(128) __half g_fh[(size_t)FDIM * IDIM];
__device__ __align__(128) __half g_ph[(size_t)PDIM * IDIM];
__device__ __align__(128) __nv_bfloat16 g_a[(size_t)BDIM * FDIM];  // xf*relu(xf)
__device__ __align__(128) __nv_bfloat16 g_w[(size_t)BDIM * FDIM];  // -beta*(1-relu(xf))
__device__ __align__(128) __nv_bfloat16 g_v[(size_t)PDIM * FDIM];  // theta*c - alpha*(1-relu(pf))
__device__ __align__(128) __nv_bfloat16 g_c[(size_t)PDIM * FDIM];  // pf*relu(pf)

// ---------------- helpers ----------------
__device__ __forceinline__ uint32_t s2u(const void* p) {
    uint32_t a;
    asm("{ .reg .u64 t; cvta.to.shared.u64 t, %1; cvt.u32.u64 %0, t; }" : "=r"(a) : "l"(p));
    return a;
}

#define CP16(dst, src) \
    asm volatile("cp.async.cg.shared.global [%0], [%1], 16;" :: "r"(dst), "l"(src))
#define CPCOMMIT() asm volatile("cp.async.commit_group;")
#define CPWAIT(n)  asm volatile("cp.async.wait_group %0;" :: "n"(n))

__device__ __forceinline__ void ldsm4(uint32_t& r0, uint32_t& r1, uint32_t& r2, uint32_t& r3,
                                      uint32_t addr) {
    asm volatile("ldmatrix.sync.aligned.m8n8.x4.shared.b16 {%0,%1,%2,%3}, [%4];"
                 : "=r"(r0), "=r"(r1), "=r"(r2), "=r"(r3) : "r"(addr));
}

__device__ __forceinline__ void mma_f16(float c[4], const uint32_t a[4], const uint32_t b[2]) {
    asm volatile(
        "mma.sync.aligned.m16n8k16.row.col.f32.f16.f16.f32 "
        "{%0,%1,%2,%3}, {%4,%5,%6,%7}, {%8,%9}, {%0,%1,%2,%3};"
        : "+f"(c[0]), "+f"(c[1]), "+f"(c[2]), "+f"(c[3])
        : "r"(a[0]), "r"(a[1]), "r"(a[2]), "r"(a[3]), "r"(b[0]), "r"(b[1]));
}

__device__ __forceinline__ void mma_bf16(float c[4], const uint32_t a[4], const uint32_t b[2]) {
    asm volatile(
        "mma.sync.aligned.m16n8k16.row.col.f32.bf16.bf16.f32 "
        "{%0,%1,%2,%3}, {%4,%5,%6,%7}, {%8,%9}, {%0,%1,%2,%3};"
        : "+f"(c[0]), "+f"(c[1]), "+f"(c[2]), "+f"(c[3])
        : "r"(a[0]), "r"(a[1]), "r"(a[2]), "r"(a[3]), "r"(b[0]), "r"(b[1]));
}

// ---------------- merged fp32 -> fp16 conversion (one launch) ----------------
__global__ void cvt_all(const float4* __restrict__ x, const float4* __restrict__ f,
                        const float4* __restrict__ p)
{
    const int nx = BDIM * IDIM / 4, nf = FDIM * IDIM / 4, np = PDIM * IDIM / 4;
    int i = blockIdx.x * blockDim.x + threadIdx.x;
    const float4* src; uint2* dst; int j;
    if (i < nx)                { src = x; dst = (uint2*)g_xh; j = i; }
    else if (i < nx + nf)      { src = f; dst = (uint2*)g_fh; j = i - nx; }
    else if (i < nx + nf + np) { src = p; dst = (uint2*)g_ph; j = i - nx - nf; }
    else return;
    float4 v = src[j];
    __half2 h0 = __floats2half2_rn(v.x, v.y);
    __half2 h1 = __floats2half2_rn(v.z, v.w);
    uint2 o; o.x = *(uint32_t*)&h0; o.y = *(uint32_t*)&h1;
    dst[j] = o;
}

// =================================================================
// Stage 1 (fp16 m16n8k16): Y = In @ Feat^T, merged x/proto grids.
// CTA 128x256, 256 threads, 8 warps (2x4), warp tile 64x64,
// k-tile 32, 4-stage cp.async, fragment double-buffering. 1 CTA/SM.
//   x-side  (rb<32): g_a = y*p,                    g_w = -beta*(1-p)
//   p-side (rb>=32): g_v = theta*y*p - alpha*(1-p), g_c = y*p
// =================================================================
#define SROW 40                            // 32 data + 8 pad halfs (80 B row)
#define S1_STAGE_E (384 * SROW)            // 128 A rows + 256 B rows
#define S1_STAGE_B (S1_STAGE_E * 2)        // 30720 bytes
#define STAGES1 4
#define S1_SMEM (STAGES1 * S1_STAGE_B)     // 122880 bytes

__global__ __launch_bounds__(256, 1)
void s1_kernel(const float* __restrict__ alpha, const float* __restrict__ beta,
               const float* __restrict__ theta)
{
    extern __shared__ __half sm1[];
    const uint32_t sb = s2u(sm1);
    const int tid = threadIdx.x;
    const int wid = tid >> 5, lid = tid & 31;
    const int g = lid >> 2, tg = lid & 3;
    const int wm = wid >> 2, wn = wid & 3;              // 2 x 4 warps, warp 64x64
    const int rb = blockIdx.y;
    const bool isX = rb < (BDIM / 128);
    const int row0 = (isX ? rb : rb - BDIM / 128) * 128;
    const int col0 = blockIdx.x * 256;

    const __half* In = isX ? g_xh : g_ph;
    __nv_bfloat16* out1 = isX ? g_a : g_v;
    __nv_bfloat16* out2 = isX ? g_w : g_c;

    // loader: 1536 cp16 per stage / 256 threads = 6 each (2 A rows + 4 B rows)
    const int r0 = tid >> 2, ch = tid & 3;              // r0: 0..63, ch: 0..3
    const __half* srcA = In   + (size_t)(row0 + r0) * IDIM + ch * 8;
    const __half* srcB = g_fh + (size_t)(col0 + r0) * IDIM + ch * 8;
    const int dBase = r0 * SROW + ch * 8;

    const int aOff = ((lid & 7) + ((lid >> 3) & 1) * 8) * SROW + (lid >> 4) * 8;
    const int bOff = ((lid & 7) + (lid >> 4) * 8) * SROW + ((lid >> 3) & 1) * 8;

    float acc[4][8][4];
#pragma unroll
    for (int mi = 0; mi < 4; mi++)
#pragma unroll
        for (int ni = 0; ni < 8; ni++)
#pragma unroll
            for (int j = 0; j < 4; j++) acc[mi][ni][j] = 0.f;

    const int NIT = IDIM / 32;   // 32

#pragma unroll
    for (int s = 0; s < STAGES1 - 1; s++) {
        __half* st = sm1 + s * S1_STAGE_E;
        const int k0 = s * 32;
#pragma unroll
        for (int i = 0; i < 2; i++)
            CP16(s2u(st + dBase + i * 64 * SROW), srcA + (size_t)(i * 64) * IDIM + k0);
#pragma unroll
        for (int i = 0; i < 4; i++)
            CP16(s2u(st + dBase + (128 + i * 64) * SROW), srcB + (size_t)(i * 64) * IDIM + k0);
        CPCOMMIT();
    }

    for (int it = 0; it < NIT; it++) {
        CPWAIT(STAGES1 - 2);
        __syncthreads();

        const int nxt = it + STAGES1 - 1;
        if (nxt < NIT) {
            __half* st = sm1 + (nxt % STAGES1) * S1_STAGE_E;
            const int k0 = nxt * 32;
#pragma unroll
            for (int i = 0; i < 2; i++)
                CP16(s2u(st + dBase + i * 64 * SROW), srcA + (size_t)(i * 64) * IDIM + k0);
#pragma unroll
            for (int i = 0; i < 4; i++)
                CP16(s2u(st + dBase + (128 + i * 64) * SROW), srcB + (size_t)(i * 64) * IDIM + k0);
        }
        CPCOMMIT();

        const uint32_t su = sb + (it % STAGES1) * S1_STAGE_B;
        const uint32_t aBase = su + 2 * (wm * 64 * SROW + aOff);
        const uint32_t bBase = su + 2 * ((128 + wn * 64) * SROW + bOff);

        uint32_t af[2][4][4], bf[2][8][2];
#pragma unroll
        for (int mi = 0; mi < 4; mi++)
            ldsm4(af[0][mi][0], af[0][mi][1], af[0][mi][2], af[0][mi][3],
                  aBase + 2 * (mi * 16 * SROW));
#pragma unroll
        for (int nb = 0; nb < 4; nb++)
            ldsm4(bf[0][2 * nb][0], bf[0][2 * nb][1], bf[0][2 * nb + 1][0], bf[0][2 * nb + 1][1],
                  bBase + 2 * (nb * 16 * SROW));

#pragma unroll
        for (int ks = 0; ks < 2; ks++) {
            const int cur = ks & 1, nx2 = cur ^ 1;
            if (ks < 1) {
                const int kk = 16;
#pragma unroll
                for (int mi = 0; mi < 4; mi++)
                    ldsm4(af[nx2][mi][0], af[nx2][mi][1], af[nx2][mi][2], af[nx2][mi][3],
                          aBase + 2 * (mi * 16 * SROW + kk));
#pragma unroll
                for (int nb = 0; nb < 4; nb++)
                    ldsm4(bf[nx2][2 * nb][0], bf[nx2][2 * nb][1],
                          bf[nx2][2 * nb + 1][0], bf[nx2][2 * nb + 1][1],
                          bBase + 2 * (nb * 16 * SROW + kk));
            }
#pragma unroll
            for (int mi = 0; mi < 4; mi++)
#pragma unroll
                for (int ni = 0; ni < 8; ni++)
                    mma_f16(acc[mi][ni], af[cur][mi], bf[cur][ni]);
        }
    }

    const float al = __ldg(alpha);
    const float be = __ldg(beta);
    const float th = __ldg(theta);

#pragma unroll
    for (int mi = 0; mi < 4; mi++)
#pragma unroll
        for (int ni = 0; ni < 8; ni++) {
            const int rr = row0 + wm * 64 + mi * 16 + g;
            const int cc = col0 + wn * 64 + ni * 8 + tg * 2;
#pragma unroll
            for (int h = 0; h < 2; h++) {
                const float y0 = acc[mi][ni][h * 2 + 0];
                const float y1 = acc[mi][ni][h * 2 + 1];
                const float p0 = fmaxf(y0, 0.f), p1 = fmaxf(y1, 0.f);
                const float yp0 = y0 * p0, yp1 = y1 * p1;
                const float iv0 = 1.f - p0, iv1 = 1.f - p1;
                float o1a, o1b, o2a, o2b;
                if (isX) { o1a = yp0;                  o1b = yp1;
                           o2a = -be * iv0;            o2b = -be * iv1; }
                else     { o1a = th * yp0 - al * iv0;  o1b = th * yp1 - al * iv1;
                           o2a = yp0;                  o2b = yp1; }
                const size_t off = (size_t)(rr + h * 8) * FDIM + cc;
                *(__nv_bfloat162*)&out1[off] = __floats2bfloat162_rn(o1a, o1b);
                *(__nv_bfloat162*)&out2[off] = __floats2bfloat162_rn(o2a, o2b);
            }
        }
}

// =================================================================
// Stage 2 (bf16 m16n8k16): out = a @ v^T + w @ c^T (two k-phases over F)
// CTA 128x64, k-tile 32, 3-stage cp.async, 128 threads, 4 warps (2x2),
// warp 64x32, fragment double-buffering.  (proven round-8/9 shape)
// =================================================================
#define STAGES2 3
#define S2_STAGE_E (192 * SROW)            // 128 A rows + 64 B rows
#define S2_STAGE_B (S2_STAGE_E * 2)        // 15360 bytes
#define S2_SMEM    (STAGES2 * S2_STAGE_B)  // 46080 bytes
#define NIT2 (2 * FDIM / 32)               // 128
#define HALF2N (FDIM / 32)                 // 64

__global__ __launch_bounds__(128, 4)
void s2_kernel(float* __restrict__ Out)
{
    extern __shared__ __nv_bfloat16 sm2[];
    const uint32_t sb = s2u(sm2);
    const int tid = threadIdx.x;
    const int wid = tid >> 5, lid = tid & 31;
    const int g = lid >> 2, tg = lid & 3;
    const int wm = wid >> 1, wn = wid & 1;              // 2 x 2 warps, warp 64x32
    const int row0 = blockIdx.y * 128;
    const int col0 = blockIdx.x * 64;

    const int r0 = tid >> 2, ch = tid & 3;
    const int dBase = r0 * SROW + ch * 8;

    const int aOff = ((lid & 7) + ((lid >> 3) & 1) * 8) * SROW + (lid >> 4) * 8;
    const int bOff = ((lid & 7) + (lid >> 4) * 8) * SROW + ((lid >> 3) & 1) * 8;

    float acc[4][4][4];
#pragma unroll
    for (int mi = 0; mi < 4; mi++)
#pragma unroll
        for (int ni = 0; ni < 4; ni++)
#pragma unroll
            for (int j = 0; j < 4; j++) acc[mi][ni][j] = 0.f;

#pragma unroll
    for (int s = 0; s < STAGES2 - 1; s++) {
        __nv_bfloat16* st = sm2 + s * S2_STAGE_E;
        const __nv_bfloat16* A = (s < HALF2N) ? g_a : g_w;
        const __nv_bfloat16* B = (s < HALF2N) ? g_v : g_c;
        const int k0 = (s & (HALF2N - 1)) * 32;
#pragma unroll
        for (int i = 0; i < 4; i++)
            CP16(s2u(st + dBase + i * 32 * SROW),
                 A + (size_t)(row0 + r0 + i * 32) * FDIM + k0 + ch * 8);
#pragma unroll
        for (int i = 0; i < 2; i++)
            CP16(s2u(st + dBase + (128 + i * 32) * SROW),
                 B + (size_t)(col0 + r0 + i * 32) * FDIM + k0 + ch * 8);
        CPCOMMIT();
    }

    for (int it = 0; it < NIT2; it++) {
        CPWAIT(STAGES2 - 2);
        __syncthreads();

        const int nxt = it + STAGES2 - 1;
        if (nxt < NIT2) {
            __nv_bfloat16* st = sm2 + (nxt % STAGES2) * S2_STAGE_E;
            const __nv_bfloat16* A = (nxt < HALF2N) ? g_a : g_w;
            const __nv_bfloat16* B = (nxt < HALF2N) ? g_v : g_c;
            const int k0 = (nxt & (HALF2N - 1)) * 32;
#pragma unroll
            for (int i = 0; i < 4; i++)
                CP16(s2u(st + dBase + i * 32 * SROW),
                     A + (size_t)(row0 + r0 + i * 32) * FDIM + k0 + ch * 8);
#pragma unroll
            for (int i = 0; i < 2; i++)
                CP16(s2u(st + dBase + (128 + i * 32) * SROW),
                     B + (size_t)(col0 + r0 + i * 32) * FDIM + k0 + ch * 8);
        }
        CPCOMMIT();

        const uint32_t su = sb + (it % STAGES2) * S2_STAGE_B;
        const uint32_t aBase = su + 2 * (wm * 64 * SROW + aOff);
        const uint32_t bBase = su + 2 * ((128 + wn * 32) * SROW + bOff);

        uint32_t af[2][4][4], bf[2][4][2];
#pragma unroll
        for (int mi = 0; mi < 4; mi++)
            ldsm4(af[0][mi][0], af[0][mi][1], af[0][mi][2], af[0][mi][3],
                  aBase + 2 * (mi * 16 * SROW));
#pragma unroll
        for (int nb = 0; nb < 2; nb++)
            ldsm4(bf[0][2 * nb][0], bf[0][2 * nb][1], bf[0][2 * nb + 1][0], bf[0][2 * nb + 1][1],
                  bBase + 2 * (nb * 16 * SROW));

#pragma unroll
        for (int ks = 0; ks < 2; ks++) {
            const int cur = ks & 1, nx2 = cur ^ 1;
            if (ks < 1) {
                const int kk = 16;
#pragma unroll
                for (int mi = 0; mi < 4; mi++)
                    ldsm4(af[nx2][mi][0], af[nx2][mi][1], af[nx2][mi][2], af[nx2][mi][3],
                          aBase + 2 * (mi * 16 * SROW + kk));
#pragma unroll
                for (int nb = 0; nb < 2; nb++)
                    ldsm4(bf[nx2][2 * nb][0], bf[nx2][2 * nb][1],
                          bf[nx2][2 * nb + 1][0], bf[nx2][2 * nb + 1][1],
                          bBase + 2 * (nb * 16 * SROW + kk));
            }
#pragma unroll
            for (int mi = 0; mi < 4; mi++)
#pragma unroll
                for (int ni = 0; ni < 4; ni++)
                    mma_bf16(acc[mi][ni], af[cur][mi], bf[cur][ni]);
        }
    }

#pragma unroll
    for (int mi = 0; mi < 4; mi++)
#pragma unroll
        for (int ni = 0; ni < 4; ni++) {
            const int rr = row0 + wm * 64 + mi * 16 + g;
            const int cc = col0 + wn * 32 + ni * 8 + tg * 2;
#pragma unroll
            for (int h = 0; h < 2; h++) {
                float2 o = { acc[mi][ni][h * 2 + 0], acc[mi][ni][h * 2 + 1] };
                *(float2*)&Out[(size_t)(rr + h * 8) * PDIM + cc] = o;
            }
        }
}

// ---------------- launch ----------------
extern "C" void kernel_launch(void* const* d_in, const int* in_sizes, int n_in,
                              void* d_out, int out_size)
{
    const float* x     = (const float*)d_in[0];
    const float* feat  = (const float*)d_in[1];
    const float* proto = (const float*)d_in[2];
    const float* alpha = (const float*)d_in[3];
    const float* beta  = (const float*)d_in[4];
    const float* theta = (const float*)d_in[5];
    float* out = (float*)d_out;

    static bool attr_done = false;
    if (!attr_done) {
        cudaFuncSetAttribute(s1_kernel, cudaFuncAttributeMaxDynamicSharedMemorySize, S1_SMEM);
        cudaFuncSetAttribute(s2_kernel, cudaFuncAttributeMaxDynamicSharedMemorySize, S2_SMEM);
        attr_done = true;
    }

    const int ntot = (BDIM + FDIM + PDIM) * IDIM / 4;
    cvt_all<<<(ntot + 255) / 256, 256>>>((const float4*)x, (const float4*)feat,
                                         (const float4*)proto);
    s1_kernel<<<dim3(FDIM / 256, (BDIM + PDIM) / 128), 256, S1_SMEM>>>(alpha, beta, theta);
    s2_kernel<<<dim3(PDIM / 64, BDIM / 128), 128, S2_SMEM>>>(out);
}

// round 13
// speedup vs baseline: 1.1140x; 1.0250x over previous
#include <cuda_runtime.h>
#include <cuda_fp16.h>
#include <cuda_bf16.h>
#include <stdint.h>

#define BDIM 4096
#define PDIM 512
#define IDIM 1024
#define FDIM 2048

// ---------------- scratch (device globals; allocation-free rule) ----------------
__device__ __align__(128) __half g_xh[(size_t)BDIM * IDIM];
__device__ __align__(128) __half g_fh[(size_t)FDIM * IDIM];
__device__ __align__(128) __half g_ph[(size_t)PDIM * IDIM];
__device__ __align__(128) __nv_bfloat16 g_a[(size_t)BDIM * FDIM];  // xf*relu(xf)
__device__ __align__(128) __nv_bfloat16 g_w[(size_t)BDIM * FDIM];  // -beta*(1-relu(xf))
__device__ __align__(128) __nv_bfloat16 g_v[(size_t)PDIM * FDIM];  // theta*c - alpha*(1-relu(pf))
__device__ __align__(128) __nv_bfloat16 g_c[(size_t)PDIM * FDIM];  // pf*relu(pf)

// ---------------- helpers ----------------
__device__ __forceinline__ uint32_t s2u(const void* p) {
    uint32_t a;
    asm("{ .reg .u64 t; cvta.to.shared.u64 t, %1; cvt.u32.u64 %0, t; }" : "=r"(a) : "l"(p));
    return a;
}

#define CP16(dst, src) \
    asm volatile("cp.async.cg.shared.global [%0], [%1], 16;" :: "r"(dst), "l"(src))
#define CPCOMMIT() asm volatile("cp.async.commit_group;")
#define CPWAIT(n)  asm volatile("cp.async.wait_group %0;" :: "n"(n))

__device__ __forceinline__ void ldsm4(uint32_t& r0, uint32_t& r1, uint32_t& r2, uint32_t& r3,
                                      uint32_t addr) {
    asm volatile("ldmatrix.sync.aligned.m8n8.x4.shared.b16 {%0,%1,%2,%3}, [%4];"
                 : "=r"(r0), "=r"(r1), "=r"(r2), "=r"(r3) : "r"(addr));
}

__device__ __forceinline__ void mma_f16(float c[4], const uint32_t a[4], const uint32_t b[2]) {
    asm volatile(
        "mma.sync.aligned.m16n8k16.row.col.f32.f16.f16.f32 "
        "{%0,%1,%2,%3}, {%4,%5,%6,%7}, {%8,%9}, {%0,%1,%2,%3};"
        : "+f"(c[0]), "+f"(c[1]), "+f"(c[2]), "+f"(c[3])
        : "r"(a[0]), "r"(a[1]), "r"(a[2]), "r"(a[3]), "r"(b[0]), "r"(b[1]));
}

__device__ __forceinline__ void mma_bf16(float c[4], const uint32_t a[4], const uint32_t b[2]) {
    asm volatile(
        "mma.sync.aligned.m16n8k16.row.col.f32.bf16.bf16.f32 "
        "{%0,%1,%2,%3}, {%4,%5,%6,%7}, {%8,%9}, {%0,%1,%2,%3};"
        : "+f"(c[0]), "+f"(c[1]), "+f"(c[2]), "+f"(c[3])
        : "r"(a[0]), "r"(a[1]), "r"(a[2]), "r"(a[3]), "r"(b[0]), "r"(b[1]));
}

// ---------------- merged fp32 -> fp16 conversion (one launch) ----------------
__global__ void cvt_all(const float4* __restrict__ x, const float4* __restrict__ f,
                        const float4* __restrict__ p)
{
    const int nx = BDIM * IDIM / 4, nf = FDIM * IDIM / 4, np = PDIM * IDIM / 4;
    int i = blockIdx.x * blockDim.x + threadIdx.x;
    const float4* src; uint2* dst; int j;
    if (i < nx)                { src = x; dst = (uint2*)g_xh; j = i; }
    else if (i < nx + nf)      { src = f; dst = (uint2*)g_fh; j = i - nx; }
    else if (i < nx + nf + np) { src = p; dst = (uint2*)g_ph; j = i - nx - nf; }
    else return;
    float4 v = src[j];
    __half2 h0 = __floats2half2_rn(v.x, v.y);
    __half2 h1 = __floats2half2_rn(v.z, v.w);
    uint2 o; o.x = *(uint32_t*)&h0; o.y = *(uint32_t*)&h1;
    dst[j] = o;
}

// =================================================================
// Stage 1 (fp16 m16n8k16): Y = In @ Feat^T, merged x/proto grids.
// CTA 128x128, 128 threads, 4 warps (2x2), warp tile 64x64,
// k-tile 32, 4-stage cp.async, fragment double-buffering. (round-9 optimum)
// =================================================================
#define SROW 40                            // 32 data + 8 pad halfs (80 B row)
#define S1_STAGE_E (256 * SROW)
#define S1_STAGE_B (S1_STAGE_E * 2)        // 20480 bytes
#define STAGES1 4
#define S1_SMEM (STAGES1 * S1_STAGE_B)     // 81920 bytes

__global__ __launch_bounds__(128, 2)
void s1_kernel(const float* __restrict__ alpha, const float* __restrict__ beta,
               const float* __restrict__ theta)
{
    extern __shared__ __half sm1[];
    const uint32_t sb = s2u(sm1);
    const int tid = threadIdx.x;
    const int wid = tid >> 5, lid = tid & 31;
    const int g = lid >> 2, tg = lid & 3;
    const int wm = wid >> 1, wn = wid & 1;
    const int rb = blockIdx.y;
    const bool isX = rb < (BDIM / 128);
    const int row0 = (isX ? rb : rb - BDIM / 128) * 128;
    const int col0 = blockIdx.x * 128;

    const __half* In = isX ? g_xh : g_ph;
    __nv_bfloat16* out1 = isX ? g_a : g_v;
    __nv_bfloat16* out2 = isX ? g_w : g_c;

    const int r0 = tid >> 2, ch = tid & 3;
    const __half* srcA = In   + (size_t)(row0 + r0) * IDIM + ch * 8;
    const __half* srcB = g_fh + (size_t)(col0 + r0) * IDIM + ch * 8;
    const int dBase = r0 * SROW + ch * 8;

    const int aOff = ((lid & 7) + ((lid >> 3) & 1) * 8) * SROW + (lid >> 4) * 8;
    const int bOff = ((lid & 7) + (lid >> 4) * 8) * SROW + ((lid >> 3) & 1) * 8;

    float acc[4][8][4];
#pragma unroll
    for (int mi = 0; mi < 4; mi++)
#pragma unroll
        for (int ni = 0; ni < 8; ni++)
#pragma unroll
            for (int j = 0; j < 4; j++) acc[mi][ni][j] = 0.f;

    const int NIT = IDIM / 32;

#pragma unroll
    for (int s = 0; s < STAGES1 - 1; s++) {
        __half* st = sm1 + s * S1_STAGE_E;
        const int k0 = s * 32;
#pragma unroll
        for (int i = 0; i < 4; i++) {
            CP16(s2u(st + dBase + i * 32 * SROW), srcA + (size_t)(i * 32) * IDIM + k0);
            CP16(s2u(st + dBase + (128 + i * 32) * SROW), srcB + (size_t)(i * 32) * IDIM + k0);
        }
        CPCOMMIT();
    }

    for (int it = 0; it < NIT; it++) {
        CPWAIT(STAGES1 - 2);
        __syncthreads();

        const int nxt = it + STAGES1 - 1;
        if (nxt < NIT) {
            __half* st = sm1 + (nxt % STAGES1) * S1_STAGE_E;
            const int k0 = nxt * 32;
#pragma unroll
            for (int i = 0; i < 4; i++) {
                CP16(s2u(st + dBase + i * 32 * SROW), srcA + (size_t)(i * 32) * IDIM + k0);
                CP16(s2u(st + dBase + (128 + i * 32) * SROW), srcB + (size_t)(i * 32) * IDIM + k0);
            }
        }
        CPCOMMIT();

        const uint32_t su = sb + (it % STAGES1) * S1_STAGE_B;
        const uint32_t aBase = su + 2 * (wm * 64 * SROW + aOff);
        const uint32_t bBase = su + 2 * ((128 + wn * 64) * SROW + bOff);

        uint32_t af[2][4][4], bf[2][8][2];
#pragma unroll
        for (int mi = 0; mi < 4; mi++)
            ldsm4(af[0][mi][0], af[0][mi][1], af[0][mi][2], af[0][mi][3],
                  aBase + 2 * (mi * 16 * SROW));
#pragma unroll
        for (int nb = 0; nb < 4; nb++)
            ldsm4(bf[0][2 * nb][0], bf[0][2 * nb][1], bf[0][2 * nb + 1][0], bf[0][2 * nb + 1][1],
                  bBase + 2 * (nb * 16 * SROW));

#pragma unroll
        for (int ks = 0; ks < 2; ks++) {
            const int cur = ks & 1, nx2 = cur ^ 1;
            if (ks < 1) {
                const int kk = 16;
#pragma unroll
                for (int mi = 0; mi < 4; mi++)
                    ldsm4(af[nx2][mi][0], af[nx2][mi][1], af[nx2][mi][2], af[nx2][mi][3],
                          aBase + 2 * (mi * 16 * SROW + kk));
#pragma unroll
                for (int nb = 0; nb < 4; nb++)
                    ldsm4(bf[nx2][2 * nb][0], bf[nx2][2 * nb][1],
                          bf[nx2][2 * nb + 1][0], bf[nx2][2 * nb + 1][1],
                          bBase + 2 * (nb * 16 * SROW + kk));
            }
#pragma unroll
            for (int mi = 0; mi < 4; mi++)
#pragma unroll
                for (int ni = 0; ni < 8; ni++)
                    mma_f16(acc[mi][ni], af[cur][mi], bf[cur][ni]);
        }
    }

    const float al = __ldg(alpha);
    const float be = __ldg(beta);
    const float th = __ldg(theta);

#pragma unroll
    for (int mi = 0; mi < 4; mi++)
#pragma unroll
        for (int ni = 0; ni < 8; ni++) {
            const int rr = row0 + wm * 64 + mi * 16 + g;
            const int cc = col0 + wn * 64 + ni * 8 + tg * 2;
#pragma unroll
            for (int h = 0; h < 2; h++) {
                const float y0 = acc[mi][ni][h * 2 + 0];
                const float y1 = acc[mi][ni][h * 2 + 1];
                const float p0 = fmaxf(y0, 0.f), p1 = fmaxf(y1, 0.f);
                const float yp0 = y0 * p0, yp1 = y1 * p1;
                const float iv0 = 1.f - p0, iv1 = 1.f - p1;
                float o1a, o1b, o2a, o2b;
                if (isX) { o1a = yp0;                  o1b = yp1;
                           o2a = -be * iv0;            o2b = -be * iv1; }
                else     { o1a = th * yp0 - al * iv0;  o1b = th * yp1 - al * iv1;
                           o2a = yp0;                  o2b = yp1; }
                const size_t off = (size_t)(rr + h * 8) * FDIM + cc;
                *(__nv_bfloat162*)&out1[off] = __floats2bfloat162_rn(o1a, o1b);
                *(__nv_bfloat162*)&out2[off] = __floats2bfloat162_rn(o2a, o2b);
            }
        }
}

// =================================================================
// Stage 2 (bf16 m16n8k16): out = a @ v^T + w @ c^T (two k-phases over F)
// CTA 128x128, 128 threads, 4 warps (2x2), warp tile 64x64,
// k-tile 32, 4-stage cp.async, fragment double-buffering.
// Same structure as s1; grid 4x32 = 128 CTAs (single wave, port unshared).
// =================================================================
#define STAGES2 4
#define S2_STAGE_E (256 * SROW)            // 128 A rows + 128 B rows
#define S2_STAGE_B (S2_STAGE_E * 2)        // 20480 bytes
#define S2_SMEM    (STAGES2 * S2_STAGE_B)  // 81920 bytes
#define NIT2 (2 * FDIM / 32)               // 128
#define HALF2N (FDIM / 32)                 // 64

__global__ __launch_bounds__(128, 2)
void s2_kernel(float* __restrict__ Out)
{
    extern __shared__ __nv_bfloat16 sm2[];
    const uint32_t sb = s2u(sm2);
    const int tid = threadIdx.x;
    const int wid = tid >> 5, lid = tid & 31;
    const int g = lid >> 2, tg = lid & 3;
    const int wm = wid >> 1, wn = wid & 1;              // 2 x 2 warps, warp 64x64
    const int row0 = blockIdx.y * 128;
    const int col0 = blockIdx.x * 128;

    const int r0 = tid >> 2, ch = tid & 3;              // r0: 0..31, ch: 0..3
    const int dBase = r0 * SROW + ch * 8;

    const int aOff = ((lid & 7) + ((lid >> 3) & 1) * 8) * SROW + (lid >> 4) * 8;
    const int bOff = ((lid & 7) + (lid >> 4) * 8) * SROW + ((lid >> 3) & 1) * 8;

    float acc[4][8][4];
#pragma unroll
    for (int mi = 0; mi < 4; mi++)
#pragma unroll
        for (int ni = 0; ni < 8; ni++)
#pragma unroll
            for (int j = 0; j < 4; j++) acc[mi][ni][j] = 0.f;

#pragma unroll
    for (int s = 0; s < STAGES2 - 1; s++) {
        __nv_bfloat16* st = sm2 + s * S2_STAGE_E;
        const __nv_bfloat16* A = (s < HALF2N) ? g_a : g_w;
        const __nv_bfloat16* B = (s < HALF2N) ? g_v : g_c;
        const int k0 = (s & (HALF2N - 1)) * 32;
#pragma unroll
        for (int i = 0; i < 4; i++) {
            CP16(s2u(st + dBase + i * 32 * SROW),
                 A + (size_t)(row0 + r0 + i * 32) * FDIM + k0 + ch * 8);
            CP16(s2u(st + dBase + (128 + i * 32) * SROW),
                 B + (size_t)(col0 + r0 + i * 32) * FDIM + k0 + ch * 8);
        }
        CPCOMMIT();
    }

    for (int it = 0; it < NIT2; it++) {
        CPWAIT(STAGES2 - 2);
        __syncthreads();

        const int nxt = it + STAGES2 - 1;
        if (nxt < NIT2) {
            __nv_bfloat16* st = sm2 + (nxt % STAGES2) * S2_STAGE_E;
            const __nv_bfloat16* A = (nxt < HALF2N) ? g_a : g_w;
            const __nv_bfloat16* B = (nxt < HALF2N) ? g_v : g_c;
            const int k0 = (nxt & (HALF2N - 1)) * 32;
#pragma unroll
            for (int i = 0; i < 4; i++) {
                CP16(s2u(st + dBase + i * 32 * SROW),
                     A + (size_t)(row0 + r0 + i * 32) * FDIM + k0 + ch * 8);
                CP16(s2u(st + dBase + (128 + i * 32) * SROW),
                     B + (size_t)(col0 + r0 + i * 32) * FDIM + k0 + ch * 8);
            }
        }
        CPCOMMIT();

        const uint32_t su = sb + (it % STAGES2) * S2_STAGE_B;
        const uint32_t aBase = su + 2 * (wm * 64 * SROW + aOff);
        const uint32_t bBase = su + 2 * ((128 + wn * 64) * SROW + bOff);

        uint32_t af[2][4][4], bf[2][8][2];
#pragma unroll
        for (int mi = 0; mi < 4; mi++)
            ldsm4(af[0][mi][0], af[0][mi][1], af[0][mi][2], af[0][mi][3],
                  aBase + 2 * (mi * 16 * SROW));
#pragma unroll
        for (int nb = 0; nb < 4; nb++)
            ldsm4(bf[0][2 * nb][0], bf[0][2 * nb][1], bf[0][2 * nb + 1][0], bf[0][2 * nb + 1][1],
                  bBase + 2 * (nb * 16 * SROW));

#pragma unroll
        for (int ks = 0; ks < 2; ks++) {
            const int cur = ks & 1, nx2 = cur ^ 1;
            if (ks < 1) {
                const int kk = 16;
#pragma unroll
                for (int mi = 0; mi < 4; mi++)
                    ldsm4(af[nx2][mi][0], af[nx2][mi][1], af[nx2][mi][2], af[nx2][mi][3],
                          aBase + 2 * (mi * 16 * SROW + kk));
#pragma unroll
                for (int nb = 0; nb < 4; nb++)
                    ldsm4(bf[nx2][2 * nb][0], bf[nx2][2 * nb][1],
                          bf[nx2][2 * nb + 1][0], bf[nx2][2 * nb + 1][1],
                          bBase + 2 * (nb * 16 * SROW + kk));
            }
#pragma unroll
            for (int mi = 0; mi < 4; mi++)
#pragma unroll
                for (int ni = 0; ni < 8; ni++)
                    mma_bf16(acc[mi][ni], af[cur][mi], bf[cur][ni]);
        }
    }

#pragma unroll
    for (int mi = 0; mi < 4; mi++)
#pragma unroll
        for (int ni = 0; ni < 8; ni++) {
            const int rr = row0 + wm * 64 + mi * 16 + g;
            const int cc = col0 + wn * 64 + ni * 8 + tg * 2;
#pragma unroll
            for (int h = 0; h < 2; h++) {
                float2 o = { acc[mi][ni][h * 2 + 0], acc[mi][ni][h * 2 + 1] };
                *(float2*)&Out[(size_t)(rr + h * 8) * PDIM + cc] = o;
            }
        }
}

// ---------------- launch ----------------
extern "C" void kernel_launch(void* const* d_in, const int* in_sizes, int n_in,
                              void* d_out, int out_size)
{
    const float* x     = (const float*)d_in[0];
    const float* feat  = (const float*)d_in[1];
    const float* proto = (const float*)d_in[2];
    const float* alpha = (const float*)d_in[3];
    const float* beta  = (const float*)d_in[4];
    const float* theta = (const float*)d_in[5];
    float* out = (float*)d_out;

    static bool attr_done = false;
    if (!attr_done) {
        cudaFuncSetAttribute(s1_kernel, cudaFuncAttributeMaxDynamicSharedMemorySize, S1_SMEM);
        cudaFuncSetAttribute(s2_kernel, cudaFuncAttributeMaxDynamicSharedMemorySize, S2_SMEM);
        attr_done = true;
    }

    const int ntot = (BDIM + FDIM + PDIM) * IDIM / 4;
    cvt_all<<<(ntot + 255) / 256, 256>>>((const float4*)x, (const float4*)feat,
                                         (const float4*)proto);
    s1_kernel<<<dim3(FDIM / 128, (BDIM + PDIM) / 128), 128, S1_SMEM>>>(alpha, beta, theta);
    s2_kernel<<<dim3(PDIM / 128, BDIM / 128), 128, S2_SMEM>>>(out);
}

// round 16
// speedup vs baseline: 1.3226x; 1.1872x over previous
#include <cuda_runtime.h>
#include <cuda_fp16.h>
#include <cuda_bf16.h>
#include <stdint.h>

#define BDIM 4096
#define PDIM 512
#define IDIM 1024
#define FDIM 2048

// ---------------- scratch (device globals; allocation-free rule) ----------------
__device__ __align__(128) __half g_xh[(size_t)BDIM * IDIM];
__device__ __align__(128) __half g_fh[(size_t)FDIM * IDIM];
__device__ __align__(128) __half g_ph[(size_t)PDIM * IDIM];
__device__ __align__(128) __nv_bfloat16 g_a[(size_t)BDIM * FDIM];  // xf*relu(xf)
__device__ __align__(128) __nv_bfloat16 g_w[(size_t)BDIM * FDIM];  // -beta*(1-relu(xf))
__device__ __align__(128) __nv_bfloat16 g_v[(size_t)PDIM * FDIM];  // theta*c - alpha*(1-relu(pf))
__device__ __align__(128) __nv_bfloat16 g_c[(size_t)PDIM * FDIM];  // pf*relu(pf)
__device__ __align__(128) float g_t2[(size_t)BDIM * PDIM];         // split-K partial (w@c^T)

// ---------------- helpers ----------------
__device__ __forceinline__ uint32_t s2u(const void* p) {
    uint32_t a;
    asm("{ .reg .u64 t; cvta.to.shared.u64 t, %1; cvt.u32.u64 %0, t; }" : "=r"(a) : "l"(p));
    return a;
}

#define CP16(dst, src) \
    asm volatile("cp.async.cg.shared.global [%0], [%1], 16;" :: "r"(dst), "l"(src))
#define CPCOMMIT() asm volatile("cp.async.commit_group;")
#define CPWAIT(n)  asm volatile("cp.async.wait_group %0;" :: "n"(n))

__device__ __forceinline__ void ldsm4(uint32_t& r0, uint32_t& r1, uint32_t& r2, uint32_t& r3,
                                      uint32_t addr) {
    asm volatile("ldmatrix.sync.aligned.m8n8.x4.shared.b16 {%0,%1,%2,%3}, [%4];"
                 : "=r"(r0), "=r"(r1), "=r"(r2), "=r"(r3) : "r"(addr));
}

__device__ __forceinline__ void mma_f16(float c[4], const uint32_t a[4], const uint32_t b[2]) {
    asm volatile(
        "mma.sync.aligned.m16n8k16.row.col.f32.f16.f16.f32 "
        "{%0,%1,%2,%3}, {%4,%5,%6,%7}, {%8,%9}, {%0,%1,%2,%3};"
        : "+f"(c[0]), "+f"(c[1]), "+f"(c[2]), "+f"(c[3])
        : "r"(a[0]), "r"(a[1]), "r"(a[2]), "r"(a[3]), "r"(b[0]), "r"(b[1]));
}

__device__ __forceinline__ void mma_bf16(float c[4], const uint32_t a[4], const uint32_t b[2]) {
    asm volatile(
        "mma.sync.aligned.m16n8k16.row.col.f32.bf16.bf16.f32 "
        "{%0,%1,%2,%3}, {%4,%5,%6,%7}, {%8,%9}, {%0,%1,%2,%3};"
        : "+f"(c[0]), "+f"(c[1]), "+f"(c[2]), "+f"(c[3])
        : "r"(a[0]), "r"(a[1]), "r"(a[2]), "r"(a[3]), "r"(b[0]), "r"(b[1]));
}

// ---------------- merged fp32 -> fp16 conversion (one launch) ----------------
__global__ void cvt_all(const float4* __restrict__ x, const float4* __restrict__ f,
                        const float4* __restrict__ p)
{
    const int nx = BDIM * IDIM / 4, nf = FDIM * IDIM / 4, np = PDIM * IDIM / 4;
    int i = blockIdx.x * blockDim.x + threadIdx.x;
    const float4* src; uint2* dst; int j;
    if (i < nx)                { src = x; dst = (uint2*)g_xh; j = i; }
    else if (i < nx + nf)      { src = f; dst = (uint2*)g_fh; j = i - nx; }
    else if (i < nx + nf + np) { src = p; dst = (uint2*)g_ph; j = i - nx - nf; }
    else return;
    float4 v = src[j];
    __half2 h0 = __floats2half2_rn(v.x, v.y);
    __half2 h1 = __floats2half2_rn(v.z, v.w);
    uint2 o; o.x = *(uint32_t*)&h0; o.y = *(uint32_t*)&h1;
    dst[j] = o;
}

// ---------------- final combine: Out += partial ----------------
__global__ void add_kernel(float4* __restrict__ Out)
{
    int i = blockIdx.x * blockDim.x + threadIdx.x;
    if (i < BDIM * PDIM / 4) {
        float4 a = Out[i];
        float4 b = ((const float4*)g_t2)[i];
        a.x += b.x; a.y += b.y; a.z += b.z; a.w += b.w;
        Out[i] = a;
    }
}

// =================================================================
// Stage 1 (fp16 m16n8k16): Y = In @ Feat^T, merged x/proto grids.
// CTA 128x128, 128 threads, 4 warps (2x2), warp tile 64x64,
// k-tile 32, 4-stage cp.async, fragment double-buffering. (round-9 optimum)
// =================================================================
#define SROW 40                            // 32 data + 8 pad halfs (80 B row)
#define S1_STAGE_E (256 * SROW)
#define S1_STAGE_B (S1_STAGE_E * 2)        // 20480 bytes
#define STAGES1 4
#define S1_SMEM (STAGES1 * S1_STAGE_B)     // 81920 bytes

__global__ __launch_bounds__(128, 2)
void s1_kernel(const float* __restrict__ alpha, const float* __restrict__ beta,
               const float* __restrict__ theta)
{
    extern __shared__ __half sm1[];
    const uint32_t sb = s2u(sm1);
    const int tid = threadIdx.x;
    const int wid = tid >> 5, lid = tid & 31;
    const int g = lid >> 2, tg = lid & 3;
    const int wm = wid >> 1, wn = wid & 1;
    const int rb = blockIdx.y;
    const bool isX = rb < (BDIM / 128);
    const int row0 = (isX ? rb : rb - BDIM / 128) * 128;
    const int col0 = blockIdx.x * 128;

    const __half* In = isX ? g_xh : g_ph;
    __nv_bfloat16* out1 = isX ? g_a : g_v;
    __nv_bfloat16* out2 = isX ? g_w : g_c;

    const int r0 = tid >> 2, ch = tid & 3;
    const __half* srcA = In   + (size_t)(row0 + r0) * IDIM + ch * 8;
    const __half* srcB = g_fh + (size_t)(col0 + r0) * IDIM + ch * 8;
    const int dBase = r0 * SROW + ch * 8;

    const int aOff = ((lid & 7) + ((lid >> 3) & 1) * 8) * SROW + (lid >> 4) * 8;
    const int bOff = ((lid & 7) + (lid >> 4) * 8) * SROW + ((lid >> 3) & 1) * 8;

    float acc[4][8][4];
#pragma unroll
    for (int mi = 0; mi < 4; mi++)
#pragma unroll
        for (int ni = 0; ni < 8; ni++)
#pragma unroll
            for (int j = 0; j < 4; j++) acc[mi][ni][j] = 0.f;

    const int NIT = IDIM / 32;

#pragma unroll
    for (int s = 0; s < STAGES1 - 1; s++) {
        __half* st = sm1 + s * S1_STAGE_E;
        const int k0 = s * 32;
#pragma unroll
        for (int i = 0; i < 4; i++) {
            CP16(s2u(st + dBase + i * 32 * SROW), srcA + (size_t)(i * 32) * IDIM + k0);
            CP16(s2u(st + dBase + (128 + i * 32) * SROW), srcB + (size_t)(i * 32) * IDIM + k0);
        }
        CPCOMMIT();
    }

    for (int it = 0; it < NIT; it++) {
        CPWAIT(STAGES1 - 2);
        __syncthreads();

        const int nxt = it + STAGES1 - 1;
        if (nxt < NIT) {
            __half* st = sm1 + (nxt % STAGES1) * S1_STAGE_E;
            const int k0 = nxt * 32;
#pragma unroll
            for (int i = 0; i < 4; i++) {
                CP16(s2u(st + dBase + i * 32 * SROW), srcA + (size_t)(i * 32) * IDIM + k0);
                CP16(s2u(st + dBase + (128 + i * 32) * SROW), srcB + (size_t)(i * 32) * IDIM + k0);
            }
        }
        CPCOMMIT();

        const uint32_t su = sb + (it % STAGES1) * S1_STAGE_B;
        const uint32_t aBase = su + 2 * (wm * 64 * SROW + aOff);
        const uint32_t bBase = su + 2 * ((128 + wn * 64) * SROW + bOff);

        uint32_t af[2][4][4], bf[2][8][2];
#pragma unroll
        for (int mi = 0; mi < 4; mi++)
            ldsm4(af[0][mi][0], af[0][mi][1], af[0][mi][2], af[0][mi][3],
                  aBase + 2 * (mi * 16 * SROW));
#pragma unroll
        for (int nb = 0; nb < 4; nb++)
            ldsm4(bf[0][2 * nb][0], bf[0][2 * nb][1], bf[0][2 * nb + 1][0], bf[0][2 * nb + 1][1],
                  bBase + 2 * (nb * 16 * SROW));

#pragma unroll
        for (int ks = 0; ks < 2; ks++) {
            const int cur = ks & 1, nx2 = cur ^ 1;
            if (ks < 1) {
                const int kk = 16;
#pragma unroll
                for (int mi = 0; mi < 4; mi++)
                    ldsm4(af[nx2][mi][0], af[nx2][mi][1], af[nx2][mi][2], af[nx2][mi][3],
                          aBase + 2 * (mi * 16 * SROW + kk));
#pragma unroll
                for (int nb = 0; nb < 4; nb++)
                    ldsm4(bf[nx2][2 * nb][0], bf[nx2][2 * nb][1],
                          bf[nx2][2 * nb + 1][0], bf[nx2][2 * nb + 1][1],
                          bBase + 2 * (nb * 16 * SROW + kk));
            }
#pragma unroll
            for (int mi = 0; mi < 4; mi++)
#pragma unroll
                for (int ni = 0; ni < 8; ni++)
                    mma_f16(acc[mi][ni], af[cur][mi], bf[cur][ni]);
        }
    }

    const float al = __ldg(alpha);
    const float be = __ldg(beta);
    const float th = __ldg(theta);

#pragma unroll
    for (int mi = 0; mi < 4; mi++)
#pragma unroll
        for (int ni = 0; ni < 8; ni++) {
            const int rr = row0 + wm * 64 + mi * 16 + g;
            const int cc = col0 + wn * 64 + ni * 8 + tg * 2;
#pragma unroll
            for (int h = 0; h < 2; h++) {
                const float y0 = acc[mi][ni][h * 2 + 0];
                const float y1 = acc[mi][ni][h * 2 + 1];
                const float p0 = fmaxf(y0, 0.f), p1 = fmaxf(y1, 0.f);
                const float yp0 = y0 * p0, yp1 = y1 * p1;
                const float iv0 = 1.f - p0, iv1 = 1.f - p1;
                float o1a, o1b, o2a, o2b;
                if (isX) { o1a = yp0;                  o1b = yp1;
                           o2a = -be * iv0;            o2b = -be * iv1; }
                else     { o1a = th * yp0 - al * iv0;  o1b = th * yp1 - al * iv1;
                           o2a = yp0;                  o2b = yp1; }
                const size_t off = (size_t)(rr + h * 8) * FDIM + cc;
                *(__nv_bfloat162*)&out1[off] = __floats2bfloat162_rn(o1a, o1b);
                *(__nv_bfloat162*)&out2[off] = __floats2bfloat162_rn(o2a, o2b);
            }
        }
}

// =================================================================
// Stage 2 (bf16 m16n8k16, split-K over the two phases):
//   z=0: Out  = a @ v^T   (K=2048)
//   z=1: g_t2 = w @ c^T   (K=2048)
// CTA 128x128, 128 threads, 4 warps (2x2), warp tile 64x64,
// k-tile 32, 4-stage cp.async, fragment double-buffering.
// Grid (4, 32, 2) = 256 CTAs -> 2 CTAs/SM co-resident.
// =================================================================
#define STAGES2 4
#define S2_STAGE_E (256 * SROW)            // 128 A rows + 128 B rows
#define S2_STAGE_B (S2_STAGE_E * 2)        // 20480 bytes
#define S2_SMEM    (STAGES2 * S2_STAGE_B)  // 81920 bytes
#define NIT2 (FDIM / 32)                   // 64 per phase

__global__ __launch_bounds__(128, 2)
void s2_kernel(float* __restrict__ Out)
{
    extern __shared__ __nv_bfloat16 sm2[];
    const uint32_t sb = s2u(sm2);
    const int tid = threadIdx.x;
    const int wid = tid >> 5, lid = tid & 31;
    const int g = lid >> 2, tg = lid & 3;
    const int wm = wid >> 1, wn = wid & 1;              // 2 x 2 warps, warp 64x64
    const int row0 = blockIdx.y * 128;
    const int col0 = blockIdx.x * 128;
    const int ph = blockIdx.z;                          // 0: a@v, 1: w@c

    const __nv_bfloat16* A = ph ? g_w : g_a;
    const __nv_bfloat16* B = ph ? g_c : g_v;
    float* Dst = ph ? g_t2 : Out;

    const int r0 = tid >> 2, ch = tid & 3;              // r0: 0..31, ch: 0..3
    const __nv_bfloat16* srcA = A + (size_t)(row0 + r0) * FDIM + ch * 8;
    const __nv_bfloat16* srcB = B + (size_t)(col0 + r0) * FDIM + ch * 8;
    const int dBase = r0 * SROW + ch * 8;

    const int aOff = ((lid & 7) + ((lid >> 3) & 1) * 8) * SROW + (lid >> 4) * 8;
    const int bOff = ((lid & 7) + (lid >> 4) * 8) * SROW + ((lid >> 3) & 1) * 8;

    float acc[4][8][4];
#pragma unroll
    for (int mi = 0; mi < 4; mi++)
#pragma unroll
        for (int ni = 0; ni < 8; ni++)
#pragma unroll
            for (int j = 0; j < 4; j++) acc[mi][ni][j] = 0.f;

#pragma unroll
    for (int s = 0; s < STAGES2 - 1; s++) {
        __nv_bfloat16* st = sm2 + s * S2_STAGE_E;
        const int k0 = s * 32;
#pragma unroll
        for (int i = 0; i < 4; i++) {
            CP16(s2u(st + dBase + i * 32 * SROW), srcA + (size_t)(i * 32) * FDIM + k0);
            CP16(s2u(st + dBase + (128 + i * 32) * SROW), srcB + (size_t)(i * 32) * FDIM + k0);
        }
        CPCOMMIT();
    }

    for (int it = 0; it < NIT2; it++) {
        CPWAIT(STAGES2 - 2);
        __syncthreads();

        const int nxt = it + STAGES2 - 1;
        if (nxt < NIT2) {
            __nv_bfloat16* st = sm2 + (nxt % STAGES2) * S2_STAGE_E;
            const int k0 = nxt * 32;
#pragma unroll
            for (int i = 0; i < 4; i++) {
                CP16(s2u(st + dBase + i * 32 * SROW), srcA + (size_t)(i * 32) * FDIM + k0);
                CP16(s2u(st + dBase + (128 + i * 32) * SROW), srcB + (size_t)(i * 32) * FDIM + k0);
            }
        }
        CPCOMMIT();

        const uint32_t su = sb + (it % STAGES2) * S2_STAGE_B;
        const uint32_t aBase = su + 2 * (wm * 64 * SROW + aOff);
        const uint32_t bBase = su + 2 * ((128 + wn * 64) * SROW + bOff);

        uint32_t af[2][4][4], bf[2][8][2];
#pragma unroll
        for (int mi = 0; mi < 4; mi++)
            ldsm4(af[0][mi][0], af[0][mi][1], af[0][mi][2], af[0][mi][3],
                  aBase + 2 * (mi * 16 * SROW));
#pragma unroll
        for (int nb = 0; nb < 4; nb++)
            ldsm4(bf[0][2 * nb][0], bf[0][2 * nb][1], bf[0][2 * nb + 1][0], bf[0][2 * nb + 1][1],
                  bBase + 2 * (nb * 16 * SROW));

#pragma unroll
        for (int ks = 0; ks < 2; ks++) {
            const int cur = ks & 1, nx2 = cur ^ 1;
            if (ks < 1) {
                const int kk = 16;
#pragma unroll
                for (int mi = 0; mi < 4; mi++)
                    ldsm4(af[nx2][mi][0], af[nx2][mi][1], af[nx2][mi][2], af[nx2][mi][3],
                          aBase + 2 * (mi * 16 * SROW + kk));
#pragma unroll
                for (int nb = 0; nb < 4; nb++)
                    ldsm4(bf[nx2][2 * nb][0], bf[nx2][2 * nb][1],
                          bf[nx2][2 * nb + 1][0], bf[nx2][2 * nb + 1][1],
                          bBase + 2 * (nb * 16 * SROW + kk));
            }
#pragma unroll
            for (int mi = 0; mi < 4; mi++)
#pragma unroll
                for (int ni = 0; ni < 8; ni++)
                    mma_bf16(acc[mi][ni], af[cur][mi], bf[cur][ni]);
        }
    }

#pragma unroll
    for (int mi = 0; mi < 4; mi++)
#pragma unroll
        for (int ni = 0; ni < 8; ni++) {
            const int rr = row0 + wm * 64 + mi * 16 + g;
            const int cc = col0 + wn * 64 + ni * 8 + tg * 2;
#pragma unroll
            for (int h = 0; h < 2; h++) {
                float2 o = { acc[mi][ni][h * 2 + 0], acc[mi][ni][h * 2 + 1] };
                *(float2*)&Dst[(size_t)(rr + h * 8) * PDIM + cc] = o;
            }
        }
}

// ---------------- launch ----------------
extern "C" void kernel_launch(void* const* d_in, const int* in_sizes, int n_in,
                              void* d_out, int out_size)
{
    const float* x     = (const float*)d_in[0];
    const float* feat  = (const float*)d_in[1];
    const float* proto = (const float*)d_in[2];
    const float* alpha = (const float*)d_in[3];
    const float* beta  = (const float*)d_in[4];
    const float* theta = (const float*)d_in[5];
    float* out = (float*)d_out;

    static bool attr_done = false;
    if (!attr_done) {
        cudaFuncSetAttribute(s1_kernel, cudaFuncAttributeMaxDynamicSharedMemorySize, S1_SMEM);
        cudaFuncSetAttribute(s2_kernel, cudaFuncAttributeMaxDynamicSharedMemorySize, S2_SMEM);
        attr_done = true;
    }

    const int ntot = (BDIM + FDIM + PDIM) * IDIM / 4;
    cvt_all<<<(ntot + 255) / 256, 256>>>((const float4*)x, (const float4*)feat,
                                         (const float4*)proto);
    s1_kernel<<<dim3(FDIM / 128, (BDIM + PDIM) / 128), 128, S1_SMEM>>>(alpha, beta, theta);
    s2_kernel<<<dim3(PDIM / 128, BDIM / 128, 2), 128, S2_SMEM>>>(out);
    add_kernel<<<(BDIM * PDIM / 4 + 255) / 256, 256>>>((float4*)out);
}